// round 4
// baseline (speedup 1.0000x reference)
#include <cuda_runtime.h>
#include <cstdint>
#include <cstring>
#include <cmath>
#include <algorithm>
#include <thread>
#include <vector>

#define TF_PARTITIONABLE 1

#define S_TOK   4608
#define HW_TOK  4096
#define NCH     256
#define MASK_W  144
#define HALF_BAND 230
#define NRAND   115

// ---------------- device scratch ----------------
__device__ float    g_feats[S_TOK * NCH];
__device__ float    g_xp0[256 * 4096];
__device__ float    g_xp1[64 * 16384];
__device__ float    g_part[8 * 256 * 256 > 16 * 64 * 256 ? 8 * 256 * 256 : 16 * 64 * 256];
__device__ float    g_y0[256 * 256];
__device__ float    g_y1[64 * 256];
__device__ float    g_qkv[S_TOK * 768];
__device__ float    g_ctx[HW_TOK * NCH];
__device__ float    g_lo[HW_TOK * NCH];
__device__ float    g_lnlo[HW_TOK * NCH];
__device__ float    g_h1[HW_TOK * 1024];
__device__ float    g_lo2[HW_TOK * NCH];
__device__ uint32_t g_mask[HW_TOK * MASK_W];

// ---------------- LN of local tokens ----------------
__global__ __launch_bounds__(256) void ln_local_k(
    const float* __restrict__ x, const float* __restrict__ pos,
    const float* __restrict__ g, const float* __restrict__ b)
{
    __shared__ float tile[256][33];
    const int t0 = blockIdx.x * 32;
    const int lane = threadIdx.x & 31, wid = threadIdx.x >> 5;
    #pragma unroll 8
    for (int it = 0; it < 32; it++) {
        int c = it * 8 + wid;
        tile[c][lane] = x[(size_t)c * HW_TOK + t0 + lane];
    }
    __syncthreads();
    for (int tt = 0; tt < 4; tt++) {
        int tok = wid * 4 + tt;
        float v[8], s = 0.f, sq = 0.f;
        #pragma unroll
        for (int i = 0; i < 8; i++) {
            int c = lane + 32 * i;
            v[i] = tile[c][tok] + pos[c];
            s += v[i]; sq += v[i] * v[i];
        }
        #pragma unroll
        for (int o = 16; o; o >>= 1) {
            s  += __shfl_xor_sync(0xffffffffu, s, o);
            sq += __shfl_xor_sync(0xffffffffu, sq, o);
        }
        float m = s * (1.f / 256.f);
        float var = sq * (1.f / 256.f) - m * m;
        float rs = rsqrtf(var + 1e-5f);
        #pragma unroll
        for (int i = 0; i < 8; i++) {
            int c = lane + 32 * i;
            g_feats[(size_t)(t0 + tok) * NCH + c] = (v[i] - m) * rs * g[c] + b[c];
        }
    }
}

// ---------------- row LN (256 cols), optional adds, optional row replication ----------------
__global__ __launch_bounds__(256) void ln_rows_k(
    const float* __restrict__ in, const float* __restrict__ add1, const float* __restrict__ add2,
    const float* __restrict__ g, const float* __restrict__ b,
    float* __restrict__ out, int rep)
{
    int row = blockIdx.x, c = threadIdx.x;
    float v = in[(size_t)row * 256 + c];
    if (add1) v += add1[c];
    if (add2) v += add2[c];
    float s = v, sq = v * v;
    #pragma unroll
    for (int o = 16; o; o >>= 1) {
        s  += __shfl_xor_sync(0xffffffffu, s, o);
        sq += __shfl_xor_sync(0xffffffffu, sq, o);
    }
    __shared__ float ss[8], qq[8];
    int wid = c >> 5, lane = c & 31;
    if (!lane) { ss[wid] = s; qq[wid] = sq; }
    __syncthreads();
    float ts = 0.f, tq = 0.f;
    #pragma unroll
    for (int i = 0; i < 8; i++) { ts += ss[i]; tq += qq[i]; }
    float m = ts * (1.f / 256.f);
    float var = tq * (1.f / 256.f) - m * m;
    float rs = rsqrtf(var + 1e-5f);
    float o = (v - m) * rs * g[c] + b[c];
    for (int k = 0; k < rep; k++)
        out[(size_t)(row * rep + k) * 256 + c] = o;
}

// ---------------- patch gathers ----------------
__global__ __launch_bounds__(256) void gather_xp0_k(const float* __restrict__ x)
{
    int idx = blockIdx.x * 256 + threadIdx.x;  // 256*4096
    int n = idx >> 12, d = idx & 4095;
    int c = d >> 4, i = (d >> 2) & 3, j = d & 3;
    int bh = n >> 4, bw = n & 15;
    g_xp0[idx] = x[(size_t)c * HW_TOK + (bh * 4 + i) * 64 + bw * 4 + j];
}
__global__ __launch_bounds__(256) void gather_xp1_k(const float* __restrict__ x)
{
    int idx = blockIdx.x * 256 + threadIdx.x;  // 64*16384
    int n = idx >> 14, d = idx & 16383;
    int c = d >> 6, i = (d >> 3) & 7, j = d & 7;
    int bh = n >> 3, bw = n & 7;
    g_xp1[idx] = x[(size_t)c * HW_TOK + (bh * 8 + i) * 64 + bw * 8 + j];
}

// ---------------- GEMM: C[M,N] = A[M,K] @ B[N,K]^T  (tiles 64x64x16) ----------------
// EPI: 1=+bias, 2=+bias+gelu, 3=+bias+residual, 4=raw split-K partial
__device__ __forceinline__ float gelu_f(float v)
{ return 0.5f * v * (1.0f + erff(v * 0.70710678118654752f)); }

template <int EPI>
__global__ __launch_bounds__(256) void gemm_k(
    const float* __restrict__ A, const float* __restrict__ B,
    const float* __restrict__ bias, const float* __restrict__ res,
    float* __restrict__ C, int M, int N, int K, int kPerZ)
{
    __shared__ float As[16][68];
    __shared__ float Bs[16][68];
    int tid = threadIdx.x;
    int bm = blockIdx.y * 64, bn = blockIdx.x * 64;
    int lrow = tid >> 2, lc4 = (tid & 3) << 2;
    int r0 = (tid >> 4) << 2, c0 = (tid & 15) << 2;
    int k0 = blockIdx.z * kPerZ;
    const float* Ap = A + (size_t)(bm + lrow) * K + k0 + lc4;
    const float* Bp = B + (size_t)(bn + lrow) * K + k0 + lc4;
    float acc[4][4] = {};
    for (int kt = 0; kt < kPerZ; kt += 16) {
        float4 a = *(const float4*)(Ap + kt);
        float4 bq = *(const float4*)(Bp + kt);
        __syncthreads();
        As[lc4 + 0][lrow] = a.x;  As[lc4 + 1][lrow] = a.y;
        As[lc4 + 2][lrow] = a.z;  As[lc4 + 3][lrow] = a.w;
        Bs[lc4 + 0][lrow] = bq.x; Bs[lc4 + 1][lrow] = bq.y;
        Bs[lc4 + 2][lrow] = bq.z; Bs[lc4 + 3][lrow] = bq.w;
        __syncthreads();
        #pragma unroll
        for (int kk = 0; kk < 16; kk++) {
            float4 av = *(const float4*)&As[kk][r0];
            float4 bv = *(const float4*)&Bs[kk][c0];
            float aa[4] = {av.x, av.y, av.z, av.w};
            float bb[4] = {bv.x, bv.y, bv.z, bv.w};
            #pragma unroll
            for (int i = 0; i < 4; i++)
                #pragma unroll
                for (int j = 0; j < 4; j++)
                    acc[i][j] += aa[i] * bb[j];
        }
    }
    float* Cz = (EPI == 4) ? (C + (size_t)blockIdx.z * M * N) : C;
    #pragma unroll
    for (int i = 0; i < 4; i++) {
        int row = bm + r0 + i;
        #pragma unroll
        for (int j = 0; j < 4; j++) {
            int col = bn + c0 + j;
            float v = acc[i][j];
            if (EPI >= 1 && EPI <= 3) v += bias[col];
            if (EPI == 2) v = gelu_f(v);
            if (EPI == 3) v += res[(size_t)row * N + col];
            Cz[(size_t)row * N + col] = v;
        }
    }
}

__global__ __launch_bounds__(256) void reduce_k(const float* __restrict__ part,
                                                float* __restrict__ out, int MN, int Z)
{
    int i = blockIdx.x * 256 + threadIdx.x;
    if (i < MN) {
        float s = 0.f;
        for (int z = 0; z < Z; z++) s += part[(size_t)z * MN + i];
        out[i] = s;
    }
}

// ---------------- dense flash attention with bitmask ----------------
__global__ __launch_bounds__(256) void attn_k(const float* __restrict__ qkv,
                                              float* __restrict__ ctx)
{
    __shared__ float Qs[32][68], Ks[32][68], Vs[64][34], Ss[64][68];
    __shared__ uint32_t mw[64][2];
    int tid = threadIdx.x;
    int h = blockIdx.y, t0 = blockIdx.x * 64;
    int ty = tid >> 4, tx = tid & 15;
    int r0 = ty * 4, c0 = tx * 4, cv0 = tx * 2;
    int lrow = tid >> 3, ld4 = (tid & 7) * 4;

    #pragma unroll
    for (int i = 0; i < 2; i++) {
        int tok = lrow + i * 32;
        float4 qv = *(const float4*)&qkv[(size_t)(t0 + tok) * 768 + h * 32 + ld4];
        Qs[ld4 + 0][tok] = qv.x; Qs[ld4 + 1][tok] = qv.y;
        Qs[ld4 + 2][tok] = qv.z; Qs[ld4 + 3][tok] = qv.w;
    }
    float m_[4], l_[4] = {0.f, 0.f, 0.f, 0.f}, o_[4][2] = {};
    #pragma unroll
    for (int i = 0; i < 4; i++) m_[i] = -INFINITY;

    const float scale = 0.17677669529663687f;  // 1/sqrt(32)

    for (int kt = 0; kt < 72; kt++) {
        __syncthreads();
        int kb = kt * 64;
        #pragma unroll
        for (int i = 0; i < 2; i++) {
            int tok = lrow + i * 32;
            float4 kv = *(const float4*)&qkv[(size_t)(kb + tok) * 768 + 256 + h * 32 + ld4];
            Ks[ld4 + 0][tok] = kv.x; Ks[ld4 + 1][tok] = kv.y;
            Ks[ld4 + 2][tok] = kv.z; Ks[ld4 + 3][tok] = kv.w;
            float4 vv = *(const float4*)&qkv[(size_t)(kb + tok) * 768 + 512 + h * 32 + ld4];
            Vs[tok][ld4 + 0] = vv.x; Vs[tok][ld4 + 1] = vv.y;
            Vs[tok][ld4 + 2] = vv.z; Vs[tok][ld4 + 3] = vv.w;
        }
        if (tid < 128)
            mw[tid >> 1][tid & 1] = g_mask[(size_t)(t0 + (tid >> 1)) * MASK_W + kt * 2 + (tid & 1)];
        __syncthreads();

        float sa[4][4] = {};
        #pragma unroll
        for (int d = 0; d < 32; d++) {
            float4 qv = *(const float4*)&Qs[d][r0];
            float4 kv = *(const float4*)&Ks[d][c0];
            float aa[4] = {qv.x, qv.y, qv.z, qv.w};
            float bb[4] = {kv.x, kv.y, kv.z, kv.w};
            #pragma unroll
            for (int i = 0; i < 4; i++)
                #pragma unroll
                for (int j = 0; j < 4; j++)
                    sa[i][j] += aa[i] * bb[j];
        }
        #pragma unroll
        for (int i = 0; i < 4; i++) {
            uint32_t bits = (mw[r0 + i][tx >> 3] >> ((tx * 4) & 31)) & 0xFu;
            float sv[4], mx = -INFINITY;
            #pragma unroll
            for (int j = 0; j < 4; j++) {
                sv[j] = ((bits >> j) & 1u) ? sa[i][j] * scale : -INFINITY;
                mx = fmaxf(mx, sv[j]);
            }
            #pragma unroll
            for (int o = 1; o < 16; o <<= 1)
                mx = fmaxf(mx, __shfl_xor_sync(0xffffffffu, mx, o));
            float mn = fmaxf(m_[i], mx);
            float al, ps = 0.f;
            if (mn == -INFINITY) {
                al = 1.f;
                #pragma unroll
                for (int j = 0; j < 4; j++) sv[j] = 0.f;
            } else {
                al = __expf(m_[i] - mn);
                #pragma unroll
                for (int j = 0; j < 4; j++) {
                    float p = (sv[j] == -INFINITY) ? 0.f : __expf(sv[j] - mn);
                    sv[j] = p; ps += p;
                }
            }
            #pragma unroll
            for (int o = 1; o < 16; o <<= 1)
                ps += __shfl_xor_sync(0xffffffffu, ps, o);
            l_[i] = l_[i] * al + ps;
            m_[i] = mn;
            o_[i][0] *= al; o_[i][1] *= al;
            Ss[r0 + i][c0 + 0] = sv[0]; Ss[r0 + i][c0 + 1] = sv[1];
            Ss[r0 + i][c0 + 2] = sv[2]; Ss[r0 + i][c0 + 3] = sv[3];
        }
        __syncthreads();
        #pragma unroll 4
        for (int j = 0; j < 64; j++) {
            float v0 = Vs[j][cv0], v1 = Vs[j][cv0 + 1];
            #pragma unroll
            for (int i = 0; i < 4; i++) {
                float p = Ss[r0 + i][j];
                o_[i][0] += p * v0; o_[i][1] += p * v1;
            }
        }
    }
    #pragma unroll
    for (int i = 0; i < 4; i++) {
        float inv = 1.f / l_[i];
        size_t base = (size_t)(t0 + r0 + i) * 256 + h * 32 + cv0;
        ctx[base] = o_[i][0] * inv;
        ctx[base + 1] = o_[i][1] * inv;
    }
}

// ---------------- final transpose + residual ----------------
__global__ __launch_bounds__(256) void finalize_k(const float* __restrict__ x,
                                                  float* __restrict__ out)
{
    __shared__ float t[32][33];
    int bhw = blockIdx.x * 32, bc = blockIdx.y * 32;
    int tx = threadIdx.x & 31, ty = threadIdx.x >> 5;
    for (int i = ty; i < 32; i += 8)
        t[i][tx] = g_lo2[(size_t)(bhw + i) * 256 + bc + tx];
    __syncthreads();
    for (int i = ty; i < 32; i += 8) {
        int c = bc + i, hw = bhw + tx;
        out[(size_t)c * HW_TOK + hw] = t[tx][i] + x[(size_t)c * HW_TOK + hw];
    }
}

// ================= host: threefry2x32 + jax mask replication =================
static inline uint32_t rotl32(uint32_t x, int r) { return (x << r) | (x >> (32 - r)); }

static void tf2x32(uint32_t k0, uint32_t k1, uint32_t x0, uint32_t x1,
                   uint32_t& o0, uint32_t& o1)
{
    uint32_t ks0 = k0, ks1 = k1, ks2 = k0 ^ k1 ^ 0x1BD11BDAu;
    static const int ra[4] = {13, 15, 26, 6}, rb[4] = {17, 29, 16, 24};
    x0 += ks0; x1 += ks1;
    for (int i = 0; i < 4; i++) { x0 += x1; x1 = rotl32(x1, ra[i]); x1 ^= x0; }
    x0 += ks1; x1 += ks2 + 1;
    for (int i = 0; i < 4; i++) { x0 += x1; x1 = rotl32(x1, rb[i]); x1 ^= x0; }
    x0 += ks2; x1 += ks0 + 2;
    for (int i = 0; i < 4; i++) { x0 += x1; x1 = rotl32(x1, ra[i]); x1 ^= x0; }
    x0 += ks0; x1 += ks1 + 3;
    for (int i = 0; i < 4; i++) { x0 += x1; x1 = rotl32(x1, rb[i]); x1 ^= x0; }
    x0 += ks1; x1 += ks2 + 4;
    for (int i = 0; i < 4; i++) { x0 += x1; x1 = rotl32(x1, ra[i]); x1 ^= x0; }
    x0 += ks2; x1 += ks0 + 5;
    o0 = x0; o1 = x1;
}

// split(key) -> (key', subkey)
static void split2(uint32_t k0, uint32_t k1,
                   uint32_t& a0, uint32_t& a1, uint32_t& s0, uint32_t& s1)
{
#if TF_PARTITIONABLE
    tf2x32(k0, k1, 0u, 0u, a0, a1);
    tf2x32(k0, k1, 0u, 1u, s0, s1);
#else
    uint32_t w0, w2, w1, w3;
    tf2x32(k0, k1, 0u, 2u, w0, w2);
    tf2x32(k0, k1, 1u, 3u, w1, w3);
    a0 = w0; a1 = w1; s0 = w2; s1 = w3;
#endif
}

// 32-bit random bits, n = S_TOK
static void bits_n(uint32_t k0, uint32_t k1, uint32_t* out)
{
#if TF_PARTITIONABLE
    for (uint32_t i = 0; i < S_TOK; i++) {
        uint32_t o0, o1;
        tf2x32(k0, k1, 0u, i, o0, o1);
        out[i] = o0 ^ o1;
    }
#else
    const uint32_t half = S_TOK / 2;
    for (uint32_t i = 0; i < half; i++) {
        uint32_t o0, o1;
        tf2x32(k0, k1, i, i + half, o0, o1);
        out[i] = o0; out[i + half] = o1;
    }
#endif
}

// row key r of split(key(42), S_TOK)
static void row_key(int r, uint32_t& k0, uint32_t& k1)
{
#if TF_PARTITIONABLE
    tf2x32(0u, 42u, 0u, (uint32_t)r, k0, k1);
#else
    uint32_t j0 = 2u * r, j1 = 2u * r + 1;
    uint32_t o0, o1;
    if (j0 < S_TOK) { tf2x32(0u, 42u, j0, j0 + S_TOK, o0, o1); k0 = o0; }
    else            { tf2x32(0u, 42u, j0 - S_TOK, j0, o0, o1); k0 = o1; }
    if (j1 < S_TOK) { tf2x32(0u, 42u, j1, j1 + S_TOK, o0, o1); k1 = o0; }
    else            { tf2x32(0u, 42u, j1 - S_TOK, j1, o0, o1); k1 = o1; }
#endif
}

static uint32_t h_mask[HW_TOK * MASK_W];

static void build_rows(int r0, int r1)
{
    std::vector<uint64_t> buf(S_TOK);
    std::vector<uint32_t> bits(S_TOK);
    std::vector<int> perm(S_TOK);
    for (int r = r0; r < r1; r++) {
        uint32_t k0, k1; row_key(r, k0, k1);
        uint32_t a0, a1, s0, s1;
        // round 1
        split2(k0, k1, a0, a1, s0, s1);
        bits_n(s0, s1, bits.data());
        for (int i = 0; i < S_TOK; i++) buf[i] = ((uint64_t)bits[i] << 32) | (uint32_t)i;
        std::sort(buf.begin(), buf.end());
        for (int i = 0; i < S_TOK; i++) perm[i] = (int)(buf[i] & 0xffffffffu);
        // round 2
        uint32_t b0, b1, t0, t1;
        split2(a0, a1, b0, b1, t0, t1);
        bits_n(t0, t1, bits.data());
        for (int i = 0; i < S_TOK; i++) buf[i] = ((uint64_t)bits[i] << 32) | (uint32_t)i;
        std::sort(buf.begin(), buf.end());
        // assemble row
        uint32_t* mrow = h_mask + (size_t)r * MASK_W;
        memset(mrow, 0, MASK_W * sizeof(uint32_t));
        int lo = r - HALF_BAND; if (lo < 0) lo = 0;
        int hi = r + HALF_BAND; if (hi > S_TOK - 1) hi = S_TOK - 1;
        for (int k = lo; k <= hi; k++) mrow[k >> 5] |= 1u << (k & 31);
        for (int i = 0; i < NRAND; i++) {
            int k = perm[(int)(buf[i] & 0xffffffffu)];
            mrow[k >> 5] |= 1u << (k & 31);
        }
    }
}

// ================= launch =================
extern "C" void kernel_launch(void* const* d_in, const int* in_sizes, int n_in,
                              void* d_out, int out_size)
{
    (void)in_sizes; (void)n_in; (void)out_size;
    const float* x         = (const float*)d_in[0];
    const float* local_pos = (const float*)d_in[1];
    const float* reg_pos0  = (const float*)d_in[2];
    const float* reg_pos1  = (const float*)d_in[3];
    const float* ln_l_g    = (const float*)d_in[4];
    const float* ln_l_b    = (const float*)d_in[5];
    const float* ln_r0_g   = (const float*)d_in[6];
    const float* ln_r0_b   = (const float*)d_in[7];
    const float* ln_r1_g   = (const float*)d_in[8];
    const float* ln_r1_b   = (const float*)d_in[9];
    const float* adj0_w    = (const float*)d_in[10];
    const float* adj0_b    = (const float*)d_in[11];
    const float* adj1_w    = (const float*)d_in[12];
    const float* adj1_b    = (const float*)d_in[13];
    const float* in_w      = (const float*)d_in[14];
    const float* in_b      = (const float*)d_in[15];
    const float* out_w     = (const float*)d_in[16];
    const float* out_b     = (const float*)d_in[17];
    const float* ln_o_g    = (const float*)d_in[18];
    const float* ln_o_b    = (const float*)d_in[19];
    const float* mlp_w1    = (const float*)d_in[20];
    const float* mlp_b1    = (const float*)d_in[21];
    const float* mlp_w2    = (const float*)d_in[22];
    const float* mlp_b2    = (const float*)d_in[23];
    float* out = (float*)d_out;

    // host mask (deterministic, recomputed every call)
    {
        unsigned hc = std::thread::hardware_concurrency();
        int nt = (int)(hc ? (hc > 64 ? 64 : hc) : 8);
        std::vector<std::thread> th;
        int per = (HW_TOK + nt - 1) / nt;
        for (int t = 0; t < nt; t++) {
            int r0 = t * per, r1 = r0 + per; if (r1 > HW_TOK) r1 = HW_TOK;
            if (r0 < r1) th.emplace_back(build_rows, r0, r1);
        }
        for (auto& t : th) t.join();
    }
    cudaMemcpyToSymbolAsync(g_mask, h_mask, sizeof(h_mask), 0, cudaMemcpyHostToDevice, 0);

    // symbol addresses
    void* p;
    cudaGetSymbolAddress(&p, g_feats); float* feats = (float*)p;
    cudaGetSymbolAddress(&p, g_xp0);   float* xp0   = (float*)p;
    cudaGetSymbolAddress(&p, g_xp1);   float* xp1   = (float*)p;
    cudaGetSymbolAddress(&p, g_part);  float* part  = (float*)p;
    cudaGetSymbolAddress(&p, g_y0);    float* y0    = (float*)p;
    cudaGetSymbolAddress(&p, g_y1);    float* y1    = (float*)p;
    cudaGetSymbolAddress(&p, g_qkv);   float* qkv   = (float*)p;
    cudaGetSymbolAddress(&p, g_ctx);   float* ctx   = (float*)p;
    cudaGetSymbolAddress(&p, g_lo);    float* lo    = (float*)p;
    cudaGetSymbolAddress(&p, g_lnlo);  float* lnlo  = (float*)p;
    cudaGetSymbolAddress(&p, g_h1);    float* h1    = (float*)p;
    cudaGetSymbolAddress(&p, g_lo2);   float* lo2   = (float*)p;

    // 1. local tokens
    ln_local_k<<<128, 256>>>(x, local_pos, ln_l_g, ln_l_b);
    // 2. regional gathers
    gather_xp0_k<<<4096, 256>>>(x);
    gather_xp1_k<<<4096, 256>>>(x);
    // 3. regional GEMMs (split-K) + LN
    gemm_k<4><<<dim3(4, 4, 8), 256>>>(xp0, adj0_w, nullptr, nullptr, part, 256, 256, 4096, 512);
    reduce_k<<<256, 256>>>(part, y0, 256 * 256, 8);
    ln_rows_k<<<256, 256>>>(y0, adj0_b, reg_pos0, ln_r0_g, ln_r0_b, feats + (size_t)4096 * 256, 1);
    gemm_k<4><<<dim3(4, 1, 16), 256>>>(xp1, adj1_w, nullptr, nullptr, part, 64, 256, 16384, 1024);
    reduce_k<<<64, 256>>>(part, y1, 64 * 256, 16);
    ln_rows_k<<<64, 256>>>(y1, adj1_b, reg_pos1, ln_r1_g, ln_r1_b, feats + (size_t)4352 * 256, 4);
    // 4. qkv projection
    gemm_k<1><<<dim3(12, 72), 256>>>(feats, in_w, in_b, nullptr, qkv, S_TOK, 768, 256, 256);
    // 5. attention (q rows 0..4095 only)
    attn_k<<<dim3(64, 8), 256>>>(qkv, ctx);
    // 6. output projection
    gemm_k<1><<<dim3(4, 64), 256>>>(ctx, out_w, out_b, nullptr, lo, HW_TOK, 256, 256, 256);
    // 7. LN + MLP
    ln_rows_k<<<4096, 256>>>(lo, nullptr, nullptr, ln_o_g, ln_o_b, lnlo, 1);
    gemm_k<2><<<dim3(16, 64), 256>>>(lnlo, mlp_w1, mlp_b1, nullptr, h1, HW_TOK, 1024, 256, 256);
    gemm_k<3><<<dim3(4, 64), 256>>>(h1, mlp_w2, mlp_b2, lo, lo2, HW_TOK, 256, 1024, 1024);
    // 8. transpose + residual
    finalize_k<<<dim3(128, 8), 256>>>(x, out);
}

// round 6
// speedup vs baseline: 2.0979x; 2.0979x over previous
#include <cuda_runtime.h>
#include <cstdint>
#include <cstring>
#include <cmath>
#include <algorithm>
#include <thread>
#include <vector>

#define TF_PARTITIONABLE 1

#define S_TOK   4608
#define HW_TOK  4096
#define NCH     256
#define MASK_W  144
#define HALF_BAND 230
#define NRAND   115
#define RAND_PITCH 116

// ---------------- device scratch ----------------
__device__ float    g_feats[S_TOK * NCH];
__device__ float    g_xp0[256 * 4096];
__device__ float    g_xp1[64 * 16384];
__device__ float    g_part[16 * 256 * 256];
__device__ float    g_y0[256 * 256];
__device__ float    g_y1[64 * 256];
__device__ float    g_qkv[S_TOK * 768];
__device__ float    g_ctx[HW_TOK * NCH];
__device__ float    g_lo[HW_TOK * NCH];
__device__ float    g_lnlo[HW_TOK * NCH];
__device__ float    g_h1[HW_TOK * 1024];
__device__ float    g_lo2[HW_TOK * NCH];
__device__ uint32_t g_mask[HW_TOK * MASK_W];
__device__ float    g_m[HW_TOK * 8];
__device__ float    g_l[HW_TOK * 8];
__device__ int      g_rand[HW_TOK * RAND_PITCH];
__device__ int      g_cnt[HW_TOK];

// ---------------- LN of local tokens ----------------
__global__ __launch_bounds__(256) void ln_local_k(
    const float* __restrict__ x, const float* __restrict__ pos,
    const float* __restrict__ g, const float* __restrict__ b)
{
    __shared__ float tile[256][33];
    const int t0 = blockIdx.x * 32;
    const int lane = threadIdx.x & 31, wid = threadIdx.x >> 5;
    #pragma unroll 8
    for (int it = 0; it < 32; it++) {
        int c = it * 8 + wid;
        tile[c][lane] = x[(size_t)c * HW_TOK + t0 + lane];
    }
    __syncthreads();
    for (int tt = 0; tt < 4; tt++) {
        int tok = wid * 4 + tt;
        float v[8], s = 0.f, sq = 0.f;
        #pragma unroll
        for (int i = 0; i < 8; i++) {
            int c = lane + 32 * i;
            v[i] = tile[c][tok] + pos[c];
            s += v[i]; sq += v[i] * v[i];
        }
        #pragma unroll
        for (int o = 16; o; o >>= 1) {
            s  += __shfl_xor_sync(0xffffffffu, s, o);
            sq += __shfl_xor_sync(0xffffffffu, sq, o);
        }
        float m = s * (1.f / 256.f);
        float var = sq * (1.f / 256.f) - m * m;
        float rs = rsqrtf(var + 1e-5f);
        #pragma unroll
        for (int i = 0; i < 8; i++) {
            int c = lane + 32 * i;
            g_feats[(size_t)(t0 + tok) * NCH + c] = (v[i] - m) * rs * g[c] + b[c];
        }
    }
}

// ---------------- row LN ----------------
__global__ __launch_bounds__(256) void ln_rows_k(
    const float* __restrict__ in, const float* __restrict__ add1, const float* __restrict__ add2,
    const float* __restrict__ g, const float* __restrict__ b,
    float* __restrict__ out, int rep)
{
    int row = blockIdx.x, c = threadIdx.x;
    float v = in[(size_t)row * 256 + c];
    if (add1) v += add1[c];
    if (add2) v += add2[c];
    float s = v, sq = v * v;
    #pragma unroll
    for (int o = 16; o; o >>= 1) {
        s  += __shfl_xor_sync(0xffffffffu, s, o);
        sq += __shfl_xor_sync(0xffffffffu, sq, o);
    }
    __shared__ float ss[8], qq[8];
    int wid = c >> 5, lane = c & 31;
    if (!lane) { ss[wid] = s; qq[wid] = sq; }
    __syncthreads();
    float ts = 0.f, tq = 0.f;
    #pragma unroll
    for (int i = 0; i < 8; i++) { ts += ss[i]; tq += qq[i]; }
    float m = ts * (1.f / 256.f);
    float var = tq * (1.f / 256.f) - m * m;
    float rs = rsqrtf(var + 1e-5f);
    float o = (v - m) * rs * g[c] + b[c];
    for (int k = 0; k < rep; k++)
        out[(size_t)(row * rep + k) * 256 + c] = o;
}

// ---------------- patch gathers ----------------
__global__ __launch_bounds__(256) void gather_xp0_k(const float* __restrict__ x)
{
    int idx = blockIdx.x * 256 + threadIdx.x;
    int n = idx >> 12, d = idx & 4095;
    int c = d >> 4, i = (d >> 2) & 3, j = d & 3;
    int bh = n >> 4, bw = n & 15;
    g_xp0[idx] = x[(size_t)c * HW_TOK + (bh * 4 + i) * 64 + bw * 4 + j];
}
__global__ __launch_bounds__(256) void gather_xp1_k(const float* __restrict__ x)
{
    int idx = blockIdx.x * 256 + threadIdx.x;
    int n = idx >> 14, d = idx & 16383;
    int c = d >> 6, i = (d >> 3) & 7, j = d & 7;
    int bh = n >> 3, bw = n & 7;
    g_xp1[idx] = x[(size_t)c * HW_TOK + (bh * 8 + i) * 64 + bw * 8 + j];
}

// ---------------- 64x64x16 GEMM (split-K path, adjacency) ----------------
__device__ __forceinline__ float gelu_f(float v)
{ return 0.5f * v * (1.0f + erff(v * 0.70710678118654752f)); }

template <int EPI>  // 4 = raw split-K partial
__global__ __launch_bounds__(256) void gemm_k(
    const float* __restrict__ A, const float* __restrict__ B,
    const float* __restrict__ bias, const float* __restrict__ res,
    float* __restrict__ C, int M, int N, int K, int kPerZ)
{
    __shared__ float As[16][68];
    __shared__ float Bs[16][68];
    int tid = threadIdx.x;
    int bm = blockIdx.y * 64, bn = blockIdx.x * 64;
    int lrow = tid >> 2, lc4 = (tid & 3) << 2;
    int r0 = (tid >> 4) << 2, c0 = (tid & 15) << 2;
    int k0 = blockIdx.z * kPerZ;
    const float* Ap = A + (size_t)(bm + lrow) * K + k0 + lc4;
    const float* Bp = B + (size_t)(bn + lrow) * K + k0 + lc4;
    float acc[4][4] = {};
    for (int kt = 0; kt < kPerZ; kt += 16) {
        float4 a = *(const float4*)(Ap + kt);
        float4 bq = *(const float4*)(Bp + kt);
        __syncthreads();
        As[lc4 + 0][lrow] = a.x;  As[lc4 + 1][lrow] = a.y;
        As[lc4 + 2][lrow] = a.z;  As[lc4 + 3][lrow] = a.w;
        Bs[lc4 + 0][lrow] = bq.x; Bs[lc4 + 1][lrow] = bq.y;
        Bs[lc4 + 2][lrow] = bq.z; Bs[lc4 + 3][lrow] = bq.w;
        __syncthreads();
        #pragma unroll
        for (int kk = 0; kk < 16; kk++) {
            float4 av = *(const float4*)&As[kk][r0];
            float4 bv = *(const float4*)&Bs[kk][c0];
            float aa[4] = {av.x, av.y, av.z, av.w};
            float bb[4] = {bv.x, bv.y, bv.z, bv.w};
            #pragma unroll
            for (int i = 0; i < 4; i++)
                #pragma unroll
                for (int j = 0; j < 4; j++)
                    acc[i][j] += aa[i] * bb[j];
        }
    }
    float* Cz = C + (size_t)blockIdx.z * M * N;
    #pragma unroll
    for (int i = 0; i < 4; i++) {
        int row = bm + r0 + i;
        #pragma unroll
        for (int j = 0; j < 4; j++)
            Cz[(size_t)row * N + bn + c0 + j] = acc[i][j];
    }
}

__global__ __launch_bounds__(256) void reduce_k(const float* __restrict__ part,
                                                float* __restrict__ out, int MN, int Z)
{
    int i = blockIdx.x * 256 + threadIdx.x;
    if (i < MN) {
        float s = 0.f;
        for (int z = 0; z < Z; z++) s += part[(size_t)z * MN + i];
        out[i] = s;
    }
}

// ---------------- 128x64x16 double-buffered GEMM ----------------
// EPI: 1=+bias, 2=+bias+gelu, 3=+bias+residual
template <int EPI>
__global__ __launch_bounds__(256) void gemm128_k(
    const float* __restrict__ A, const float* __restrict__ B,
    const float* __restrict__ bias, const float* __restrict__ res,
    float* __restrict__ C, int M, int N, int K)
{
    __shared__ float As[2][16][132];
    __shared__ float Bs[2][16][68];
    const int tid = threadIdx.x;
    const int bm = blockIdx.y * 128, bn = blockIdx.x * 64;
    const int row = tid >> 2;
    const int lc4 = (tid & 3) << 2;
    const int r0 = (tid >> 4) << 3;
    const int c0 = (tid & 15) << 2;
    const float* Ap0 = A + (size_t)(bm + row) * K + lc4;
    const float* Ap1 = A + (size_t)(bm + row + 64) * K + lc4;
    const float* Bp  = B + (size_t)(bn + row) * K + lc4;
    float acc[8][4] = {};

    float4 a0 = *(const float4*)Ap0;
    float4 a1 = *(const float4*)Ap1;
    float4 b0 = *(const float4*)Bp;
    As[0][lc4 + 0][row] = a0.x; As[0][lc4 + 1][row] = a0.y;
    As[0][lc4 + 2][row] = a0.z; As[0][lc4 + 3][row] = a0.w;
    As[0][lc4 + 0][row + 64] = a1.x; As[0][lc4 + 1][row + 64] = a1.y;
    As[0][lc4 + 2][row + 64] = a1.z; As[0][lc4 + 3][row + 64] = a1.w;
    Bs[0][lc4 + 0][row] = b0.x; Bs[0][lc4 + 1][row] = b0.y;
    Bs[0][lc4 + 2][row] = b0.z; Bs[0][lc4 + 3][row] = b0.w;
    __syncthreads();

    int cur = 0;
    for (int kt = 16; kt < K; kt += 16) {
        a0 = *(const float4*)(Ap0 + kt);
        a1 = *(const float4*)(Ap1 + kt);
        b0 = *(const float4*)(Bp + kt);
        #pragma unroll
        for (int kk = 0; kk < 16; kk++) {
            float4 av0 = *(const float4*)&As[cur][kk][r0];
            float4 av1 = *(const float4*)&As[cur][kk][r0 + 4];
            float4 bv  = *(const float4*)&Bs[cur][kk][c0];
            float aa[8] = {av0.x, av0.y, av0.z, av0.w, av1.x, av1.y, av1.z, av1.w};
            float bb[4] = {bv.x, bv.y, bv.z, bv.w};
            #pragma unroll
            for (int i = 0; i < 8; i++)
                #pragma unroll
                for (int j = 0; j < 4; j++)
                    acc[i][j] += aa[i] * bb[j];
        }
        int nxt = cur ^ 1;
        As[nxt][lc4 + 0][row] = a0.x; As[nxt][lc4 + 1][row] = a0.y;
        As[nxt][lc4 + 2][row] = a0.z; As[nxt][lc4 + 3][row] = a0.w;
        As[nxt][lc4 + 0][row + 64] = a1.x; As[nxt][lc4 + 1][row + 64] = a1.y;
        As[nxt][lc4 + 2][row + 64] = a1.z; As[nxt][lc4 + 3][row + 64] = a1.w;
        Bs[nxt][lc4 + 0][row] = b0.x; Bs[nxt][lc4 + 1][row] = b0.y;
        Bs[nxt][lc4 + 2][row] = b0.z; Bs[nxt][lc4 + 3][row] = b0.w;
        __syncthreads();
        cur = nxt;
    }
    #pragma unroll
    for (int kk = 0; kk < 16; kk++) {
        float4 av0 = *(const float4*)&As[cur][kk][r0];
        float4 av1 = *(const float4*)&As[cur][kk][r0 + 4];
        float4 bv  = *(const float4*)&Bs[cur][kk][c0];
        float aa[8] = {av0.x, av0.y, av0.z, av0.w, av1.x, av1.y, av1.z, av1.w};
        float bb[4] = {bv.x, bv.y, bv.z, bv.w};
        #pragma unroll
        for (int i = 0; i < 8; i++)
            #pragma unroll
            for (int j = 0; j < 4; j++)
                acc[i][j] += aa[i] * bb[j];
    }
    #pragma unroll
    for (int i = 0; i < 8; i++) {
        int rw = bm + r0 + i;
        #pragma unroll
        for (int j = 0; j < 4; j++) {
            int col = bn + c0 + j;
            float v = acc[i][j] + bias[col];
            if (EPI == 2) v = gelu_f(v);
            if (EPI == 3) v += res[(size_t)rw * N + col];
            C[(size_t)rw * N + col] = v;
        }
    }
}

// ---------------- band flash attention (tiles in band range only) ----------------
__global__ __launch_bounds__(256) void attn_band_k(const float* __restrict__ qkv,
                                                   float* __restrict__ ctx)
{
    __shared__ float Qs[32][68], Ks[32][68], Vs[64][34], Ss[64][68];
    __shared__ uint32_t mw[64][2];
    int tid = threadIdx.x;
    int h = blockIdx.y, t0 = blockIdx.x * 64;
    int ty = tid >> 4, tx = tid & 15;
    int r0 = ty * 4, c0 = tx * 4, cv0 = tx * 2;
    int lrow = tid >> 3, ld4 = (tid & 7) * 4;

    #pragma unroll
    for (int i = 0; i < 2; i++) {
        int tok = lrow + i * 32;
        float4 qv = *(const float4*)&qkv[(size_t)(t0 + tok) * 768 + h * 32 + ld4];
        Qs[ld4 + 0][tok] = qv.x; Qs[ld4 + 1][tok] = qv.y;
        Qs[ld4 + 2][tok] = qv.z; Qs[ld4 + 3][tok] = qv.w;
    }
    float m_[4], l_[4] = {0.f, 0.f, 0.f, 0.f}, o_[4][2] = {};
    #pragma unroll
    for (int i = 0; i < 4; i++) m_[i] = -INFINITY;

    const float scale = 0.17677669529663687f;

    int lo_t = (t0 >= HALF_BAND) ? ((t0 - HALF_BAND) >> 6) : 0;
    int hi_t = (t0 + 63 + HALF_BAND) >> 6; if (hi_t > 71) hi_t = 71;

    for (int kt = lo_t; kt <= hi_t; kt++) {
        __syncthreads();
        int kb = kt * 64;
        #pragma unroll
        for (int i = 0; i < 2; i++) {
            int tok = lrow + i * 32;
            float4 kv = *(const float4*)&qkv[(size_t)(kb + tok) * 768 + 256 + h * 32 + ld4];
            Ks[ld4 + 0][tok] = kv.x; Ks[ld4 + 1][tok] = kv.y;
            Ks[ld4 + 2][tok] = kv.z; Ks[ld4 + 3][tok] = kv.w;
            float4 vv = *(const float4*)&qkv[(size_t)(kb + tok) * 768 + 512 + h * 32 + ld4];
            Vs[tok][ld4 + 0] = vv.x; Vs[tok][ld4 + 1] = vv.y;
            Vs[tok][ld4 + 2] = vv.z; Vs[tok][ld4 + 3] = vv.w;
        }
        if (tid < 128)
            mw[tid >> 1][tid & 1] = g_mask[(size_t)(t0 + (tid >> 1)) * MASK_W + kt * 2 + (tid & 1)];
        __syncthreads();

        float sa[4][4] = {};
        #pragma unroll
        for (int d = 0; d < 32; d++) {
            float4 qv = *(const float4*)&Qs[d][r0];
            float4 kv = *(const float4*)&Ks[d][c0];
            float aa[4] = {qv.x, qv.y, qv.z, qv.w};
            float bb[4] = {kv.x, kv.y, kv.z, kv.w};
            #pragma unroll
            for (int i = 0; i < 4; i++)
                #pragma unroll
                for (int j = 0; j < 4; j++)
                    sa[i][j] += aa[i] * bb[j];
        }
        #pragma unroll
        for (int i = 0; i < 4; i++) {
            uint32_t bits = (mw[r0 + i][tx >> 3] >> ((tx * 4) & 31)) & 0xFu;
            float sv[4], mx = -INFINITY;
            #pragma unroll
            for (int j = 0; j < 4; j++) {
                sv[j] = ((bits >> j) & 1u) ? sa[i][j] * scale : -INFINITY;
                mx = fmaxf(mx, sv[j]);
            }
            #pragma unroll
            for (int o = 1; o < 16; o <<= 1)
                mx = fmaxf(mx, __shfl_xor_sync(0xffffffffu, mx, o));
            float mn = fmaxf(m_[i], mx);
            float al, ps = 0.f;
            if (mn == -INFINITY) {
                al = 1.f;
                #pragma unroll
                for (int j = 0; j < 4; j++) sv[j] = 0.f;
            } else {
                al = __expf(m_[i] - mn);
                #pragma unroll
                for (int j = 0; j < 4; j++) {
                    float p = (sv[j] == -INFINITY) ? 0.f : __expf(sv[j] - mn);
                    sv[j] = p; ps += p;
                }
            }
            #pragma unroll
            for (int o = 1; o < 16; o <<= 1)
                ps += __shfl_xor_sync(0xffffffffu, ps, o);
            l_[i] = l_[i] * al + ps;
            m_[i] = mn;
            o_[i][0] *= al; o_[i][1] *= al;
            Ss[r0 + i][c0 + 0] = sv[0]; Ss[r0 + i][c0 + 1] = sv[1];
            Ss[r0 + i][c0 + 2] = sv[2]; Ss[r0 + i][c0 + 3] = sv[3];
        }
        __syncthreads();
        #pragma unroll 4
        for (int j = 0; j < 64; j++) {
            float v0 = Vs[j][cv0], v1 = Vs[j][cv0 + 1];
            #pragma unroll
            for (int i = 0; i < 4; i++) {
                float p = Ss[r0 + i][j];
                o_[i][0] += p * v0; o_[i][1] += p * v1;
            }
        }
    }
    // write UNNORMALIZED partial state
    #pragma unroll
    for (int i = 0; i < 4; i++) {
        int row = t0 + r0 + i;
        size_t base = (size_t)row * 256 + h * 32 + cv0;
        ctx[base] = o_[i][0];
        ctx[base + 1] = o_[i][1];
        if (tx == 0) { g_m[row * 8 + h] = m_[i]; g_l[row * 8 + h] = l_[i]; }
    }
}

// ---------------- random-key pass: one block per q-row, one warp per head ----------------
__global__ __launch_bounds__(256) void attn_rand_k(const float* __restrict__ qkv,
                                                   float* __restrict__ ctx)
{
    const int row = blockIdx.x;
    const int w = threadIdx.x >> 5;      // head
    const int lane = threadIdx.x & 31;   // dim within head
    const int ch = w * 32 + lane;
    const float scale = 0.17677669529663687f;

    float qv = qkv[(size_t)row * 768 + ch];
    float m = g_m[row * 8 + w];
    float l = g_l[row * 8 + w];
    float o = ctx[(size_t)row * 256 + ch];
    int cnt = g_cnt[row];
    const int* lst = g_rand + (size_t)row * RAND_PITCH;

    if (cnt > 0) {
        int k = lst[0];
        float kv = qkv[(size_t)k * 768 + 256 + ch];
        float vv = qkv[(size_t)k * 768 + 512 + ch];
        for (int i = 0; i < cnt; i++) {
            float kv_n = 0.f, vv_n = 0.f;
            if (i + 1 < cnt) {
                int kn = lst[i + 1];
                kv_n = qkv[(size_t)kn * 768 + 256 + ch];
                vv_n = qkv[(size_t)kn * 768 + 512 + ch];
            }
            float s = qv * kv;
            #pragma unroll
            for (int off = 16; off; off >>= 1)
                s += __shfl_xor_sync(0xffffffffu, s, off);
            s *= scale;
            float mn = fmaxf(m, s);
            float al = __expf(m - mn);
            float p = __expf(s - mn);
            l = l * al + p;
            o = o * al + p * vv;
            m = mn;
            kv = kv_n; vv = vv_n;
        }
    }
    ctx[(size_t)row * 256 + ch] = o / l;
}

// ---------------- final transpose + residual ----------------
__global__ __launch_bounds__(256) void finalize_k(const float* __restrict__ x,
                                                  float* __restrict__ out)
{
    __shared__ float t[32][33];
    int bhw = blockIdx.x * 32, bc = blockIdx.y * 32;
    int tx = threadIdx.x & 31, ty = threadIdx.x >> 5;
    for (int i = ty; i < 32; i += 8)
        t[i][tx] = g_lo2[(size_t)(bhw + i) * 256 + bc + tx];
    __syncthreads();
    for (int i = ty; i < 32; i += 8) {
        int c = bc + i, hw = bhw + tx;
        out[(size_t)c * HW_TOK + hw] = t[tx][i] + x[(size_t)c * HW_TOK + hw];
    }
}

// ================= host: threefry2x32 + jax mask replication =================
static inline uint32_t rotl32(uint32_t x, int r) { return (x << r) | (x >> (32 - r)); }

static void tf2x32(uint32_t k0, uint32_t k1, uint32_t x0, uint32_t x1,
                   uint32_t& o0, uint32_t& o1)
{
    uint32_t ks0 = k0, ks1 = k1, ks2 = k0 ^ k1 ^ 0x1BD11BDAu;
    static const int ra[4] = {13, 15, 26, 6}, rb[4] = {17, 29, 16, 24};
    x0 += ks0; x1 += ks1;
    for (int i = 0; i < 4; i++) { x0 += x1; x1 = rotl32(x1, ra[i]); x1 ^= x0; }
    x0 += ks1; x1 += ks2 + 1;
    for (int i = 0; i < 4; i++) { x0 += x1; x1 = rotl32(x1, rb[i]); x1 ^= x0; }
    x0 += ks2; x1 += ks0 + 2;
    for (int i = 0; i < 4; i++) { x0 += x1; x1 = rotl32(x1, ra[i]); x1 ^= x0; }
    x0 += ks0; x1 += ks1 + 3;
    for (int i = 0; i < 4; i++) { x0 += x1; x1 = rotl32(x1, rb[i]); x1 ^= x0; }
    x0 += ks1; x1 += ks2 + 4;
    for (int i = 0; i < 4; i++) { x0 += x1; x1 = rotl32(x1, ra[i]); x1 ^= x0; }
    x0 += ks2; x1 += ks0 + 5;
    o0 = x0; o1 = x1;
}

static void split2(uint32_t k0, uint32_t k1,
                   uint32_t& a0, uint32_t& a1, uint32_t& s0, uint32_t& s1)
{
#if TF_PARTITIONABLE
    tf2x32(k0, k1, 0u, 0u, a0, a1);
    tf2x32(k0, k1, 0u, 1u, s0, s1);
#else
    uint32_t w0, w2, w1, w3;
    tf2x32(k0, k1, 0u, 2u, w0, w2);
    tf2x32(k0, k1, 1u, 3u, w1, w3);
    a0 = w0; a1 = w1; s0 = w2; s1 = w3;
#endif
}

static void bits_n(uint32_t k0, uint32_t k1, uint32_t* out)
{
#if TF_PARTITIONABLE
    for (uint32_t i = 0; i < S_TOK; i++) {
        uint32_t o0, o1;
        tf2x32(k0, k1, 0u, i, o0, o1);
        out[i] = o0 ^ o1;
    }
#else
    const uint32_t half = S_TOK / 2;
    for (uint32_t i = 0; i < half; i++) {
        uint32_t o0, o1;
        tf2x32(k0, k1, i, i + half, o0, o1);
        out[i] = o0; out[i + half] = o1;
    }
#endif
}

static void row_key(int r, uint32_t& k0, uint32_t& k1)
{
#if TF_PARTITIONABLE
    tf2x32(0u, 42u, 0u, (uint32_t)r, k0, k1);
#else
    uint32_t j0 = 2u * r, j1 = 2u * r + 1;
    uint32_t o0, o1;
    if (j0 < S_TOK) { tf2x32(0u, 42u, j0, j0 + S_TOK, o0, o1); k0 = o0; }
    else            { tf2x32(0u, 42u, j0 - S_TOK, j0, o0, o1); k0 = o1; }
    if (j1 < S_TOK) { tf2x32(0u, 42u, j1, j1 + S_TOK, o0, o1); k1 = o0; }
    else            { tf2x32(0u, 42u, j1 - S_TOK, j1, o0, o1); k1 = o1; }
#endif
}

static uint32_t h_mask[HW_TOK * MASK_W];
static int      h_rand[HW_TOK * RAND_PITCH];
static int      h_cnt[HW_TOK];

static void build_rows(int r0, int r1)
{
    std::vector<uint64_t> buf(S_TOK);
    std::vector<uint32_t> bits(S_TOK);
    std::vector<int> perm(S_TOK);
    for (int r = r0; r < r1; r++) {
        uint32_t k0, k1; row_key(r, k0, k1);
        uint32_t a0, a1, s0, s1;
        split2(k0, k1, a0, a1, s0, s1);
        bits_n(s0, s1, bits.data());
        for (int i = 0; i < S_TOK; i++) buf[i] = ((uint64_t)bits[i] << 32) | (uint32_t)i;
        std::sort(buf.begin(), buf.end());
        for (int i = 0; i < S_TOK; i++) perm[i] = (int)(buf[i] & 0xffffffffu);
        uint32_t b0, b1, t0k, t1k;
        split2(a0, a1, b0, b1, t0k, t1k);
        bits_n(t0k, t1k, bits.data());
        for (int i = 0; i < S_TOK; i++) buf[i] = ((uint64_t)bits[i] << 32) | (uint32_t)i;
        std::sort(buf.begin(), buf.end());

        uint32_t* mrow = h_mask + (size_t)r * MASK_W;
        memset(mrow, 0, MASK_W * sizeof(uint32_t));
        int lo = r - HALF_BAND; if (lo < 0) lo = 0;
        int hi = r + HALF_BAND; if (hi > S_TOK - 1) hi = S_TOK - 1;
        for (int k = lo; k <= hi; k++) mrow[k >> 5] |= 1u << (k & 31);

        // band-pass tile range for this row's q-tile (must match attn_band_k)
        int t0 = r & ~63;
        int lo_t = (t0 >= HALF_BAND) ? ((t0 - HALF_BAND) >> 6) : 0;
        int hi_t = (t0 + 63 + HALF_BAND) >> 6; if (hi_t > 71) hi_t = 71;
        int lo_b = lo_t * 64, hi_b = hi_t * 64 + 63;

        int cnt = 0;
        for (int i = 0; i < NRAND; i++) {
            int k = perm[(int)(buf[i] & 0xffffffffu)];
            mrow[k >> 5] |= 1u << (k & 31);
            if (k < lo_b || k > hi_b)
                h_rand[(size_t)r * RAND_PITCH + cnt++] = k;
        }
        h_cnt[r] = cnt;
    }
}

// ================= launch =================
extern "C" void kernel_launch(void* const* d_in, const int* in_sizes, int n_in,
                              void* d_out, int out_size)
{
    (void)in_sizes; (void)n_in; (void)out_size;
    const float* x         = (const float*)d_in[0];
    const float* local_pos = (const float*)d_in[1];
    const float* reg_pos0  = (const float*)d_in[2];
    const float* reg_pos1  = (const float*)d_in[3];
    const float* ln_l_g    = (const float*)d_in[4];
    const float* ln_l_b    = (const float*)d_in[5];
    const float* ln_r0_g   = (const float*)d_in[6];
    const float* ln_r0_b   = (const float*)d_in[7];
    const float* ln_r1_g   = (const float*)d_in[8];
    const float* ln_r1_b   = (const float*)d_in[9];
    const float* adj0_w    = (const float*)d_in[10];
    const float* adj0_b    = (const float*)d_in[11];
    const float* adj1_w    = (const float*)d_in[12];
    const float* adj1_b    = (const float*)d_in[13];
    const float* in_w      = (const float*)d_in[14];
    const float* in_b      = (const float*)d_in[15];
    const float* out_w     = (const float*)d_in[16];
    const float* out_b     = (const float*)d_in[17];
    const float* ln_o_g    = (const float*)d_in[18];
    const float* ln_o_b    = (const float*)d_in[19];
    const float* mlp_w1    = (const float*)d_in[20];
    const float* mlp_b1    = (const float*)d_in[21];
    const float* mlp_w2    = (const float*)d_in[22];
    const float* mlp_b2    = (const float*)d_in[23];
    float* out = (float*)d_out;

    {
        unsigned hc = std::thread::hardware_concurrency();
        int nt = (int)(hc ? (hc > 64 ? 64 : hc) : 8);
        std::vector<std::thread> th;
        int per = (HW_TOK + nt - 1) / nt;
        for (int t = 0; t < nt; t++) {
            int r0 = t * per, r1 = r0 + per; if (r1 > HW_TOK) r1 = HW_TOK;
            if (r0 < r1) th.emplace_back(build_rows, r0, r1);
        }
        for (auto& t : th) t.join();
    }
    cudaMemcpyToSymbolAsync(g_mask, h_mask, sizeof(h_mask), 0, cudaMemcpyHostToDevice, 0);
    cudaMemcpyToSymbolAsync(g_rand, h_rand, sizeof(h_rand), 0, cudaMemcpyHostToDevice, 0);
    cudaMemcpyToSymbolAsync(g_cnt,  h_cnt,  sizeof(h_cnt),  0, cudaMemcpyHostToDevice, 0);

    void* p;
    cudaGetSymbolAddress(&p, g_feats); float* feats = (float*)p;
    cudaGetSymbolAddress(&p, g_xp0);   float* xp0   = (float*)p;
    cudaGetSymbolAddress(&p, g_xp1);   float* xp1   = (float*)p;
    cudaGetSymbolAddress(&p, g_part);  float* part  = (float*)p;
    cudaGetSymbolAddress(&p, g_y0);    float* y0    = (float*)p;
    cudaGetSymbolAddress(&p, g_y1);    float* y1    = (float*)p;
    cudaGetSymbolAddress(&p, g_qkv);   float* qkv   = (float*)p;
    cudaGetSymbolAddress(&p, g_ctx);   float* ctx   = (float*)p;
    cudaGetSymbolAddress(&p, g_lo);    float* lo    = (float*)p;
    cudaGetSymbolAddress(&p, g_lnlo);  float* lnlo  = (float*)p;
    cudaGetSymbolAddress(&p, g_h1);    float* h1    = (float*)p;
    cudaGetSymbolAddress(&p, g_lo2);   float* lo2   = (float*)p;

    ln_local_k<<<128, 256>>>(x, local_pos, ln_l_g, ln_l_b);
    gather_xp0_k<<<4096, 256>>>(x);
    gather_xp1_k<<<4096, 256>>>(x);

    gemm_k<4><<<dim3(4, 4, 16), 256>>>(xp0, adj0_w, nullptr, nullptr, part, 256, 256, 4096, 256);
    reduce_k<<<256, 256>>>(part, y0, 256 * 256, 16);
    ln_rows_k<<<256, 256>>>(y0, adj0_b, reg_pos0, ln_r0_g, ln_r0_b, feats + (size_t)4096 * 256, 1);

    gemm_k<4><<<dim3(4, 1, 32), 256>>>(xp1, adj1_w, nullptr, nullptr, part, 64, 256, 16384, 512);
    reduce_k<<<64, 256>>>(part, y1, 64 * 256, 32);
    ln_rows_k<<<64, 256>>>(y1, adj1_b, reg_pos1, ln_r1_g, ln_r1_b, feats + (size_t)4352 * 256, 4);

    gemm128_k<1><<<dim3(12, 36), 256>>>(feats, in_w, in_b, nullptr, qkv, S_TOK, 768, 256);

    attn_band_k<<<dim3(64, 8), 256>>>(qkv, ctx);
    attn_rand_k<<<4096, 256>>>(qkv, ctx);

    gemm128_k<1><<<dim3(4, 32), 256>>>(ctx, out_w, out_b, nullptr, lo, HW_TOK, 256, 256);
    ln_rows_k<<<4096, 256>>>(lo, nullptr, nullptr, ln_o_g, ln_o_b, lnlo, 1);
    gemm128_k<2><<<dim3(16, 32), 256>>>(lnlo, mlp_w1, mlp_b1, nullptr, h1, HW_TOK, 1024, 256);
    gemm128_k<3><<<dim3(4, 32), 256>>>(h1, mlp_w2, mlp_b2, lo, lo2, HW_TOK, 256, 1024);

    finalize_k<<<dim3(128, 8), 256>>>(x, out);
}